// round 7
// baseline (speedup 1.0000x reference)
#include <cuda_runtime.h>
#include <cuda_bf16.h>
#include <cstdint>

// SiLU y = x*sigmoid(x), streaming fp32 over 4*4096*4096 elements.
// R7: Blackwell 256-bit global accesses (ld/st.global.v8.f32, sm_100a+).
// Each thread: 2 front-batched 32B loads + 2 32B stores, .cs streaming.

__device__ __forceinline__ float silu1(float x) {
    return x * (1.0f / (1.0f + __expf(-x)));
}

struct __align__(32) f8 { float v[8]; };

__device__ __forceinline__ f8 ldg256_cs(const float* p) {
    f8 r;
    asm volatile(
        "ld.global.cs.v8.f32 {%0,%1,%2,%3,%4,%5,%6,%7}, [%8];"
        : "=f"(r.v[0]), "=f"(r.v[1]), "=f"(r.v[2]), "=f"(r.v[3]),
          "=f"(r.v[4]), "=f"(r.v[5]), "=f"(r.v[6]), "=f"(r.v[7])
        : "l"(p));
    return r;
}

__device__ __forceinline__ void stg256_cs(float* p, const f8& r) {
    asm volatile(
        "st.global.cs.v8.f32 [%0], {%1,%2,%3,%4,%5,%6,%7,%8};"
        :: "l"(p),
           "f"(r.v[0]), "f"(r.v[1]), "f"(r.v[2]), "f"(r.v[3]),
           "f"(r.v[4]), "f"(r.v[5]), "f"(r.v[6]), "f"(r.v[7])
        : "memory");
}

__device__ __forceinline__ f8 silu8(f8 a) {
    f8 r;
    #pragma unroll
    for (int k = 0; k < 8; k++) r.v[k] = silu1(a.v[k]);
    return r;
}

#define TPB 256
#define V8PT 2   // two v8 (32B) accesses per thread -> 16 floats/thread

// Exact-fit: grid * TPB * 16 == n. No predicates.
__global__ void __launch_bounds__(TPB, 8)
silu_v8_exact(const float* __restrict__ in, float* __restrict__ out) {
    int64_t base = (int64_t)blockIdx.x * (TPB * V8PT * 8) + threadIdx.x * 8;
    const float* p0 = in + base;
    const float* p1 = in + base + TPB * 8;
    // Front-batched 256-bit loads
    f8 a = ldg256_cs(p0);
    f8 b = ldg256_cs(p1);
    stg256_cs(out + base,            silu8(a));
    stg256_cs(out + base + TPB * 8,  silu8(b));
}

// Guarded fallback (float4 path) for shapes that don't divide exactly.
__device__ __forceinline__ float4 silu4(float4 v) {
    float4 r;
    r.x = silu1(v.x); r.y = silu1(v.y); r.z = silu1(v.z); r.w = silu1(v.w);
    return r;
}

__global__ void __launch_bounds__(TPB, 8)
silu_guarded(const float4* __restrict__ in, float4* __restrict__ out, int n4) {
    int base = blockIdx.x * (TPB * 4) + threadIdx.x;
    #pragma unroll
    for (int k = 0; k < 4; k++) {
        int i = base + k * TPB;
        if (i < n4) __stcs(&out[i], silu4(__ldcs(&in[i])));
    }
}

__global__ void silu_tail(const float* __restrict__ in, float* __restrict__ out,
                          int start, int n) {
    int i = start + blockIdx.x * blockDim.x + threadIdx.x;
    if (i < n) out[i] = silu1(in[i]);
}

extern "C" void kernel_launch(void* const* d_in, const int* in_sizes, int n_in,
                              void* d_out, int out_size) {
    const float* x = (const float*)d_in[0];
    float* y = (float*)d_out;
    int n = in_sizes[0];

    const int per_block_v8 = TPB * V8PT * 8;  // 4096 floats per block

    if (n % per_block_v8 == 0) {
        silu_v8_exact<<<n / per_block_v8, TPB>>>(x, y);
    } else {
        int n4 = n / 4;
        if (n4 > 0) {
            int blocks = (n4 + TPB * 4 - 1) / (TPB * 4);
            silu_guarded<<<blocks, TPB>>>((const float4*)x, (float4*)y, n4);
        }
        int rem = n - n4 * 4;
        if (rem > 0) silu_tail<<<1, 256>>>(x, y, n4 * 4, n);
    }
}

// round 8
// speedup vs baseline: 1.0004x; 1.0004x over previous
#include <cuda_runtime.h>
#include <cuda_bf16.h>
#include <cstdint>

// SiLU y = x*sigmoid(x), streaming fp32 over 4*4096*4096 elements.
// R8 (final): 256-bit global accesses (Blackwell v8.f32) + 512-thread
// blocks. Exact-fit path with zero predicates, .cs streaming hints.
// Measured plateau: ~6.4 TB/s on 1:1 R/W HBM3e stream (~80% of spec,
// the practical mixed-direction ceiling).

__device__ __forceinline__ float silu1(float x) {
    return x * (1.0f / (1.0f + __expf(-x)));
}

struct __align__(32) f8 { float v[8]; };

__device__ __forceinline__ f8 ldg256_cs(const float* p) {
    f8 r;
    asm volatile(
        "ld.global.cs.v8.f32 {%0,%1,%2,%3,%4,%5,%6,%7}, [%8];"
        : "=f"(r.v[0]), "=f"(r.v[1]), "=f"(r.v[2]), "=f"(r.v[3]),
          "=f"(r.v[4]), "=f"(r.v[5]), "=f"(r.v[6]), "=f"(r.v[7])
        : "l"(p));
    return r;
}

__device__ __forceinline__ void stg256_cs(float* p, const f8& r) {
    asm volatile(
        "st.global.cs.v8.f32 [%0], {%1,%2,%3,%4,%5,%6,%7,%8};"
        :: "l"(p),
           "f"(r.v[0]), "f"(r.v[1]), "f"(r.v[2]), "f"(r.v[3]),
           "f"(r.v[4]), "f"(r.v[5]), "f"(r.v[6]), "f"(r.v[7])
        : "memory");
}

__device__ __forceinline__ f8 silu8(f8 a) {
    f8 r;
    #pragma unroll
    for (int k = 0; k < 8; k++) r.v[k] = silu1(a.v[k]);
    return r;
}

#define TPB 512
#define V8PT 2   // two 32B accesses per thread -> 16 floats/thread

// Exact-fit: grid * TPB * 16 == n. No predicates.
__global__ void __launch_bounds__(TPB, 4)
silu_v8_512(const float* __restrict__ in, float* __restrict__ out) {
    int64_t base = (int64_t)blockIdx.x * (TPB * V8PT * 8) + threadIdx.x * 8;
    // Front-batched 256-bit loads
    f8 a = ldg256_cs(in + base);
    f8 b = ldg256_cs(in + base + TPB * 8);
    stg256_cs(out + base,           silu8(a));
    stg256_cs(out + base + TPB * 8, silu8(b));
}

// Guarded float4 fallback for shapes that don't divide exactly.
__device__ __forceinline__ float4 silu4(float4 v) {
    float4 r;
    r.x = silu1(v.x); r.y = silu1(v.y); r.z = silu1(v.z); r.w = silu1(v.w);
    return r;
}

__global__ void __launch_bounds__(256, 8)
silu_guarded(const float4* __restrict__ in, float4* __restrict__ out, int n4) {
    int base = blockIdx.x * (256 * 4) + threadIdx.x;
    #pragma unroll
    for (int k = 0; k < 4; k++) {
        int i = base + k * 256;
        if (i < n4) __stcs(&out[i], silu4(__ldcs(&in[i])));
    }
}

__global__ void silu_tail(const float* __restrict__ in, float* __restrict__ out,
                          int start, int n) {
    int i = start + blockIdx.x * blockDim.x + threadIdx.x;
    if (i < n) out[i] = silu1(in[i]);
}

extern "C" void kernel_launch(void* const* d_in, const int* in_sizes, int n_in,
                              void* d_out, int out_size) {
    const float* x = (const float*)d_in[0];
    float* y = (float*)d_out;
    int n = in_sizes[0];

    const int per_block = TPB * V8PT * 8;  // 8192 floats per block

    if (n % per_block == 0) {
        silu_v8_512<<<n / per_block, TPB>>>(x, y);
    } else {
        int n4 = n / 4;
        if (n4 > 0) {
            int blocks = (n4 + 256 * 4 - 1) / (256 * 4);
            silu_guarded<<<blocks, 256>>>((const float4*)x, (float4*)y, n4);
        }
        int rem = n - n4 * 4;
        if (rem > 0) silu_tail<<<1, 256>>>(x, y, n4 * 4, n);
    }
}

// round 9
// speedup vs baseline: 1.0078x; 1.0074x over previous
#include <cuda_runtime.h>
#include <cuda_bf16.h>
#include <cstdint>

// SiLU y = x*sigmoid(x), streaming fp32 over 4*4096*4096 elements.
// R9: v8 (256-bit) global accesses + 1024-thread blocks (grid=4096,
// 2 CTAs/SM, full 2048 thr/SM). Exact-fit, zero predicates, .cs hints.
// Block-size scaling 256->512 was monotonically positive in the v8
// family; this is the final step of that axis.

__device__ __forceinline__ float silu1(float x) {
    return x * (1.0f / (1.0f + __expf(-x)));
}

struct __align__(32) f8 { float v[8]; };

__device__ __forceinline__ f8 ldg256_cs(const float* p) {
    f8 r;
    asm volatile(
        "ld.global.cs.v8.f32 {%0,%1,%2,%3,%4,%5,%6,%7}, [%8];"
        : "=f"(r.v[0]), "=f"(r.v[1]), "=f"(r.v[2]), "=f"(r.v[3]),
          "=f"(r.v[4]), "=f"(r.v[5]), "=f"(r.v[6]), "=f"(r.v[7])
        : "l"(p));
    return r;
}

__device__ __forceinline__ void stg256_cs(float* p, const f8& r) {
    asm volatile(
        "st.global.cs.v8.f32 [%0], {%1,%2,%3,%4,%5,%6,%7,%8};"
        :: "l"(p),
           "f"(r.v[0]), "f"(r.v[1]), "f"(r.v[2]), "f"(r.v[3]),
           "f"(r.v[4]), "f"(r.v[5]), "f"(r.v[6]), "f"(r.v[7])
        : "memory");
}

__device__ __forceinline__ f8 silu8(f8 a) {
    f8 r;
    #pragma unroll
    for (int k = 0; k < 8; k++) r.v[k] = silu1(a.v[k]);
    return r;
}

#define TPB 1024
#define V8PT 2   // two 32B accesses per thread -> 16 floats/thread

// Exact-fit: grid * TPB * 16 == n. No predicates.
__global__ void __launch_bounds__(TPB, 2)
silu_v8_1024(const float* __restrict__ in, float* __restrict__ out) {
    int64_t base = (int64_t)blockIdx.x * (TPB * V8PT * 8) + threadIdx.x * 8;
    // Front-batched 256-bit loads
    f8 a = ldg256_cs(in + base);
    f8 b = ldg256_cs(in + base + TPB * 8);
    stg256_cs(out + base,           silu8(a));
    stg256_cs(out + base + TPB * 8, silu8(b));
}

// Guarded float4 fallback for shapes that don't divide exactly.
__device__ __forceinline__ float4 silu4(float4 v) {
    float4 r;
    r.x = silu1(v.x); r.y = silu1(v.y); r.z = silu1(v.z); r.w = silu1(v.w);
    return r;
}

__global__ void __launch_bounds__(256, 8)
silu_guarded(const float4* __restrict__ in, float4* __restrict__ out, int n4) {
    int base = blockIdx.x * (256 * 4) + threadIdx.x;
    #pragma unroll
    for (int k = 0; k < 4; k++) {
        int i = base + k * 256;
        if (i < n4) __stcs(&out[i], silu4(__ldcs(&in[i])));
    }
}

__global__ void silu_tail(const float* __restrict__ in, float* __restrict__ out,
                          int start, int n) {
    int i = start + blockIdx.x * blockDim.x + threadIdx.x;
    if (i < n) out[i] = silu1(in[i]);
}

extern "C" void kernel_launch(void* const* d_in, const int* in_sizes, int n_in,
                              void* d_out, int out_size) {
    const float* x = (const float*)d_in[0];
    float* y = (float*)d_out;
    int n = in_sizes[0];

    const int per_block = TPB * V8PT * 8;  // 16384 floats per block

    if (n % per_block == 0) {
        silu_v8_1024<<<n / per_block, TPB>>>(x, y);
    } else {
        int n4 = n / 4;
        if (n4 > 0) {
            int blocks = (n4 + 256 * 4 - 1) / (256 * 4);
            silu_guarded<<<blocks, 256>>>((const float4*)x, (float4*)y, n4);
        }
        int rem = n - n4 * 4;
        if (rem > 0) silu_tail<<<1, 256>>>(x, y, n4 * 4, n);
    }
}